// round 9
// baseline (speedup 1.0000x reference)
#include <cuda_runtime.h>
#include <math.h>

#define B_     2048
#define S_     96
#define F_     32
#define H_     256
#define O_     6
#define LA_    32
#define WARM_  96
#define STEPS_ 128
#define MB_    14
#define PAIRS_ 7
#define NTH_   512
#define NBLK_  147        // ceil(2048 / 14); grid MUST be <= 148 (persistent CTAs)
#define KTOT_  (F_ + H_)  // 288 combined k range (x rows 0..31, h rows 32..287)
#define KHALF_ 144        // symmetric split-k per warpgroup
#define KPAD_  296        // padded weight rows: linear prefetch never OOB
#define HSTRIDE_ 20       // floats per state row: 14 data + 6 pad, 16B-aligned rows

typedef unsigned long long ull;

// Static device scratch (no allocation allowed).
__device__ float4 g_W[KPAD_ * H_];   // [k][jh] -> (i,f,g,o); k<32 from Wih, 32..287 Whh
__device__ float4 g_bias[H_];        // combined bias (i,f,g,o)

// ---- packed fp32x2 helpers ----
__device__ __forceinline__ ull ffma2(ull a, ull b, ull c) {
    ull d;
    asm("fma.rn.f32x2 %0, %1, %2, %3;" : "=l"(d) : "l"(a), "l"(b), "l"(c));
    return d;
}
__device__ __forceinline__ ull add2(ull a, ull b) {
    ull d;
    asm("add.rn.f32x2 %0, %1, %2;" : "=l"(d) : "l"(a), "l"(b));
    return d;
}
__device__ __forceinline__ ull splat2(float x) {
    ull d; unsigned u = __float_as_uint(x);
    asm("mov.b64 %0, {%1, %1};" : "=l"(d) : "r"(u));
    return d;
}
__device__ __forceinline__ float2 unpk(ull v) {
    unsigned lo, hi;
    asm("mov.b64 {%0, %1}, %2;" : "=r"(lo), "=r"(hi) : "l"(v));
    return make_float2(__uint_as_float(lo), __uint_as_float(hi));
}
__device__ __forceinline__ ull pk(float a, float b) {
    ull d;
    asm("mov.b64 %0, {%1, %2};" : "=l"(d) : "r"(__float_as_uint(a)), "r"(__float_as_uint(b)));
    return d;
}
// ACCURATE activations (fast-math fails: STE chaos amplified ~1e-6 act err to 2.4e-3)
__device__ __forceinline__ float sigf(float x) { return 1.0f / (1.0f + expf(-x)); }

// One-time weight interleave: combined (x|h) k range, 4-gate float4, bias fold.
__global__ void pack_kernel(const float* __restrict__ Wih, const float* __restrict__ Whh,
                            const float* __restrict__ bih, const float* __restrict__ bhh) {
    int idx = blockIdx.x * blockDim.x + threadIdx.x;
    if (idx >= KPAD_ * H_) return;
    int k  = idx >> 8;
    int jh = idx & 255;
    float4 v = make_float4(0.f, 0.f, 0.f, 0.f);
    if (k < F_) {
        v.x = Wih[(0 * H_ + jh) * F_ + k];
        v.y = Wih[(1 * H_ + jh) * F_ + k];
        v.z = Wih[(2 * H_ + jh) * F_ + k];
        v.w = Wih[(3 * H_ + jh) * F_ + k];
    } else if (k < KTOT_) {
        int kk = k - F_;
        v.x = Whh[(0 * H_ + jh) * H_ + kk];
        v.y = Whh[(1 * H_ + jh) * H_ + kk];
        v.z = Whh[(2 * H_ + jh) * H_ + kk];
        v.w = Whh[(3 * H_ + jh) * H_ + kk];
    }
    g_W[idx] = v;
    if (k == 0) {
        float4 b;
        b.x = bih[0 * H_ + jh] + bhh[0 * H_ + jh];
        b.y = bih[1 * H_ + jh] + bhh[1 * H_ + jh];
        b.z = bih[2 * H_ + jh] + bhh[2 * H_ + jh];
        b.w = bih[3 * H_ + jh] + bhh[3 * H_ + jh];
        g_bias[jh] = b;
    }
}

// One k-slice: 7 batch pairs x 4 gates = 28 FFMA2, fed by 3x LDS.128 + 1x LDS.64.
// (hh-array form: measured lowest alu% of all variants tried)
__device__ __forceinline__ void gemm_body(const float* __restrict__ row, float4 w,
                                          ull (&acc)[4][PAIRS_]) {
    ulonglong2 p0 = *(const ulonglong2*)(row);
    ulonglong2 p1 = *(const ulonglong2*)(row + 4);
    ulonglong2 p2 = *(const ulonglong2*)(row + 8);
    ull h6 = *(const ull*)(row + 12);
    ull hh[PAIRS_] = {p0.x, p0.y, p1.x, p1.y, p2.x, p2.y, h6};
    ull wi = splat2(w.x), wf = splat2(w.y), wg = splat2(w.z), wo = splat2(w.w);
#pragma unroll
    for (int p = 0; p < PAIRS_; p++) {
        acc[0][p] = ffma2(hh[p], wi, acc[0][p]);
        acc[1][p] = ffma2(hh[p], wf, acc[1][p]);
        acc[2][p] = ffma2(hh[p], wg, acc[2][p]);
        acc[3][p] = ffma2(hh[p], wo, acc[3][p]);
    }
}

// KN even. Linear pointer-increment prefetch into the padded weight region:
// no wrap SELs, no per-iteration index IMADs (R4's main alu cost).
template <int KN>
__device__ __forceinline__ void gemm_part(const float4* __restrict__ Wcol,
                                          const float* __restrict__ Sm,
                                          ull (&acc)[4][PAIRS_]) {
    float4 wa = __ldg(Wcol);
    float4 wb = __ldg(Wcol + H_);
    const float4* Wq = Wcol + 2 * H_;
    const float*  Sr = Sm;
#pragma unroll 1
    for (int k = 0; k < KN; k += 2) {
        float4 n0 = __ldg(Wq);
        float4 n1 = __ldg(Wq + H_);
        gemm_body(Sr, wa, acc);
        gemm_body(Sr + HSTRIDE_, wb, acc);
        wa = n0;
        wb = n1;
        Wq += 2 * H_;
        Sr += 2 * HSTRIDE_;
    }
}

// Dynamic smem layout (floats):
//   S     [288][20]       : 5760 floats  (rows 0..31 = x_t, rows 32..287 = h)
//   Ex    [256][28] ull   : 14336 floats (split-k partial exchange / readout scratch)
//   WfcS  [6][256]        : 1536
//   bfcS  [8], oS [84+pad]
#define SM_S_    0
#define SM_EX_   (SM_S_ + KTOT_ * HSTRIDE_)
#define SM_WFC_  (SM_EX_ + 256 * 28 * 2)
#define SM_BFC_  (SM_WFC_ + O_ * H_)
#define SM_OS_   (SM_BFC_ + 8)
#define SM_TOTF_ (SM_OS_ + MB_ * O_ + 4)
#define SMEM_BYTES_ (SM_TOTF_ * 4)

__global__ void __launch_bounds__(NTH_, 1)
lstm_kernel(const float* __restrict__ x, const float* __restrict__ Wfc,
            const float* __restrict__ bfc, float* __restrict__ out) {
    extern __shared__ __align__(16) float smem[];
    float* S    = smem + SM_S_;
    ull*   Ex   = (ull*)(smem + SM_EX_);     // [jh][28]  (g*7 + p)
    float* WfcS = smem + SM_WFC_;
    float* bfcS = smem + SM_BFC_;
    float* oS   = smem + SM_OS_;

    const int tid = threadIdx.x;
    const int jh  = tid & 255;
    const int wg  = tid >> 8;        // k-half: 0 -> k[0,144), 1 -> k[144,288)
    const int b0  = blockIdx.x * MB_;

    for (int i = tid; i < KTOT_ * HSTRIDE_; i += NTH_) S[i] = 0.0f;
    for (int i = tid; i < O_ * H_; i += NTH_) WfcS[i] = Wfc[i];
    if (tid < O_) bfcS[tid] = bfc[tid];

    // c state: wg0 owns pairs 0..3 (rows 0..7); wg1 pairs 4..6 (rows 8..13)
    float c[8];
#pragma unroll
    for (int r = 0; r < 8; r++) c[r] = 0.0f;

    const int pbase = wg ? 4 : 0;
    const int np    = wg ? 3 : 4;

    const float4 bias = g_bias[jh];
    const float4* __restrict__ Wcol  = g_W + (size_t)(wg * KHALF_) * H_ + jh;
    const float*  __restrict__ Sbase = S + wg * KHALF_ * HSTRIDE_;

    float* Hrow  = S + (F_ + jh) * HSTRIDE_;
    ull*   ExRow = Ex + (size_t)jh * 28;

    // ---- x stager: thread slots (f, pair), 224 slots ----
    const bool stager = tid < F_ * PAIRS_;
    int xf = 0, xp = 0;
    const float* xr0 = x;
    const float* xr1 = x;
    float xa = 0.0f, xb = 0.0f;
    if (stager) {
        xf = tid / PAIRS_;
        xp = tid - xf * PAIRS_;
        int r0 = b0 + 2 * xp;     if (r0 > B_ - 1) r0 = B_ - 1;
        int r1 = b0 + 2 * xp + 1; if (r1 > B_ - 1) r1 = B_ - 1;
        xr0 = x + (size_t)r0 * S_ * F_ + xf;
        xr1 = x + (size_t)r1 * S_ * F_ + xf;
        xa = xr0[0];
        xb = xr1[0];
    }

    __syncthreads();

    for (int t = 0; t < STEPS_; t++) {
        const bool la = (t >= WARM_);

        // ---- stage x_t into S rows 0..31 (la steps override f<6 with prev output) ----
        if (stager) {
            float v0 = xa, v1 = xb;
            if (la && xf < O_) {
                v0 = oS[(2 * xp) * O_ + xf];
                v1 = oS[(2 * xp + 1) * O_ + xf];
            }
            *(ull*)(S + xf * HSTRIDE_ + 2 * xp) = pk(v0, v1);
            int tn = t + 1;
            if (tn < STEPS_) {
                int tsn = (tn < WARM_) ? tn : (tn - WARM_);
                xa = xr0[(size_t)tsn * F_];
                xb = xr1[(size_t)tsn * F_];
            }
        }
        __syncthreads();   // x rows ready; h rows stable

        // ---- split-k 4-gate GEMM over this WG's 144 k-slices ----
        ull acc[4][PAIRS_];
        if (wg == 0) {
            ull bi = splat2(bias.x), bf = splat2(bias.y),
                bg = splat2(bias.z), bo = splat2(bias.w);
#pragma unroll
            for (int p = 0; p < PAIRS_; p++) {
                acc[0][p] = bi; acc[1][p] = bf; acc[2][p] = bg; acc[3][p] = bo;
            }
        } else {
            ull z = splat2(0.0f);
#pragma unroll
            for (int p = 0; p < PAIRS_; p++) {
                acc[0][p] = z; acc[1][p] = z; acc[2][p] = z; acc[3][p] = z;
            }
        }
        gemm_part<KHALF_>(Wcol, Sbase, acc);

        // ---- exchange complement k-half partials ----
        if (wg == 0) {            // give pairs 4..6 to wg1
#pragma unroll
            for (int g = 0; g < 4; g++)
#pragma unroll
                for (int p = 4; p < 7; p++) ExRow[g * 7 + p] = acc[g][p];
        } else {                  // give pairs 0..3 to wg0
#pragma unroll
            for (int g = 0; g < 4; g++)
#pragma unroll
                for (int p = 0; p < 4; p++) ExRow[g * 7 + p] = acc[g][p];
        }
        __syncthreads();   // partials visible; all S reads complete

        // ---- reduce own pairs + elementwise cell + write new h ----
#pragma unroll
        for (int q = 0; q < 4; q++) {
            if (q >= np) break;
            int p = pbase + q;
            float2 gi = unpk(add2(acc[0][p], ExRow[0 * 7 + p]));
            float2 gf = unpk(add2(acc[1][p], ExRow[1 * 7 + p]));
            float2 gg = unpk(add2(acc[2][p], ExRow[2 * 7 + p]));
            float2 go = unpk(add2(acc[3][p], ExRow[3 * 7 + p]));
            float c0 = sigf(gf.x) * c[2 * q]     + sigf(gi.x) * tanhf(gg.x);
            float c1 = sigf(gf.y) * c[2 * q + 1] + sigf(gi.y) * tanhf(gg.y);
            c[2 * q] = c0; c[2 * q + 1] = c1;
            *(ull*)(Hrow + 2 * p) = pk(sigf(go.x) * tanhf(c0),
                                       sigf(go.y) * tanhf(c1));
        }
        __syncthreads();   // new h complete

        // ---- STE readout: out = (h>0) @ W_fc^T + b_fc  (t = 95..127) ----
        if (t >= WARM_ - 1) {
            float* red = (float*)Ex;   // scratch [84][4] (Ex dead until next exchange)
            const float* Hs = S + F_ * HSTRIDE_;
            if (tid < MB_ * O_ * 4) {
                int slot  = tid >> 2;
                int chunk = tid & 3;
                int r  = slot / O_;
                int oi = slot - r * O_;
                const float* wrow = WfcS + oi * H_;
                float s0 = 0.0f, s1 = 0.0f;
                int jb = chunk * 64;
#pragma unroll 8
                for (int j = 0; j < 64; j += 2) {
                    s0 += (Hs[(jb + j) * HSTRIDE_ + r] > 0.0f)     ? wrow[jb + j]     : 0.0f;
                    s1 += (Hs[(jb + j + 1) * HSTRIDE_ + r] > 0.0f) ? wrow[jb + j + 1] : 0.0f;
                }
                red[slot * 4 + chunk] = s0 + s1;
            }
            __syncthreads();
            if (tid < MB_ * O_) {
                int r  = tid / O_;
                int oi = tid - r * O_;
                float a = bfcS[oi] + red[tid * 4 + 0] + red[tid * 4 + 1]
                                   + red[tid * 4 + 2] + red[tid * 4 + 3];
                oS[tid] = a;
                if (b0 + r < B_)
                    out[((size_t)(b0 + r) * (LA_ + 1) + (t - (WARM_ - 1))) * O_ + oi] = a;
            }
            __syncthreads();   // oS ready; red scratch dead before next exchange
        }
    }
}

extern "C" void kernel_launch(void* const* d_in, const int* in_sizes, int n_in,
                              void* d_out, int out_size) {
    const float* x    = (const float*)d_in[0];
    const float* W_ih = (const float*)d_in[1];
    const float* W_hh = (const float*)d_in[2];
    const float* b_ih = (const float*)d_in[3];
    const float* b_hh = (const float*)d_in[4];
    const float* W_fc = (const float*)d_in[5];
    const float* b_fc = (const float*)d_in[6];
    float* out = (float*)d_out;

    cudaFuncSetAttribute(lstm_kernel, cudaFuncAttributeMaxDynamicSharedMemorySize,
                         SMEM_BYTES_);

    pack_kernel<<<(KPAD_ * H_ + 255) / 256, 256>>>(W_ih, W_hh, b_ih, b_hh);
    lstm_kernel<<<NBLK_, NTH_, SMEM_BYTES_>>>(x, W_fc, b_fc, out);
}

// round 10
// speedup vs baseline: 1.2215x; 1.2215x over previous
#include <cuda_runtime.h>
#include <math.h>

#define B_     2048
#define S_     96
#define F_     32
#define H_     256
#define O_     6
#define LA_    32
#define WARM_  96
#define STEPS_ 128
#define MB_    14
#define PAIRS_ 7
#define NTH_   512
#define NBLK_  147        // ceil(2048 / 14); grid MUST be <= 148 (one wave)
#define KTOT_  (F_ + H_)  // 288 combined k range (x rows 0..31, h rows 32..287)
#define KHALF_ 144        // symmetric split-k per warpgroup
#define KPAD_  296        // padded weight rows: linear prefetch never OOB
#define HSTRIDE_ 18       // floats per state row: 14 data + 4 pad, 8B-aligned rows
                          // (LDS.64 only — .128 quads + 28 accs @128-reg cap => MOV blowup)

typedef unsigned long long ull;

// Static device scratch (no allocation allowed).
__device__ float4 g_W[KPAD_ * H_];   // [k][jh] -> (i,f,g,o); k<32 from Wih, 32..287 Whh
__device__ float4 g_bias[H_];        // combined bias (i,f,g,o)

// ---- packed fp32x2 helpers ----
__device__ __forceinline__ ull ffma2(ull a, ull b, ull c) {
    ull d;
    asm("fma.rn.f32x2 %0, %1, %2, %3;" : "=l"(d) : "l"(a), "l"(b), "l"(c));
    return d;
}
__device__ __forceinline__ ull add2(ull a, ull b) {
    ull d;
    asm("add.rn.f32x2 %0, %1, %2;" : "=l"(d) : "l"(a), "l"(b));
    return d;
}
__device__ __forceinline__ ull splat2(float x) {
    ull d; unsigned u = __float_as_uint(x);
    asm("mov.b64 %0, {%1, %1};" : "=l"(d) : "r"(u));
    return d;
}
__device__ __forceinline__ float2 unpk(ull v) {
    unsigned lo, hi;
    asm("mov.b64 {%0, %1}, %2;" : "=r"(lo), "=r"(hi) : "l"(v));
    return make_float2(__uint_as_float(lo), __uint_as_float(hi));
}
__device__ __forceinline__ ull pk(float a, float b) {
    ull d;
    asm("mov.b64 %0, {%1, %2};" : "=l"(d) : "r"(__float_as_uint(a)), "r"(__float_as_uint(b)));
    return d;
}
// ACCURATE activations (fast-math fails: STE chaos amplified ~1e-6 act err to 2.4e-3)
__device__ __forceinline__ float sigf(float x) { return 1.0f / (1.0f + expf(-x)); }

// One-time weight interleave: combined (x|h) k range, 4-gate float4, bias fold.
__global__ void pack_kernel(const float* __restrict__ Wih, const float* __restrict__ Whh,
                            const float* __restrict__ bih, const float* __restrict__ bhh) {
    int idx = blockIdx.x * blockDim.x + threadIdx.x;
    if (idx >= KPAD_ * H_) return;
    int k  = idx >> 8;
    int jh = idx & 255;
    float4 v = make_float4(0.f, 0.f, 0.f, 0.f);
    if (k < F_) {
        v.x = Wih[(0 * H_ + jh) * F_ + k];
        v.y = Wih[(1 * H_ + jh) * F_ + k];
        v.z = Wih[(2 * H_ + jh) * F_ + k];
        v.w = Wih[(3 * H_ + jh) * F_ + k];
    } else if (k < KTOT_) {
        int kk = k - F_;
        v.x = Whh[(0 * H_ + jh) * H_ + kk];
        v.y = Whh[(1 * H_ + jh) * H_ + kk];
        v.z = Whh[(2 * H_ + jh) * H_ + kk];
        v.w = Whh[(3 * H_ + jh) * H_ + kk];
    }
    g_W[idx] = v;
    if (k == 0) {
        float4 b;
        b.x = bih[0 * H_ + jh] + bhh[0 * H_ + jh];
        b.y = bih[1 * H_ + jh] + bhh[1 * H_ + jh];
        b.z = bih[2 * H_ + jh] + bhh[2 * H_ + jh];
        b.w = bih[3 * H_ + jh] + bhh[3 * H_ + jh];
        g_bias[jh] = b;
    }
}

// One k-slice: 7 batch pairs x 4 gates = 28 FFMA2, fed by 7x LDS.64 (broadcast).
// R3-proven codegen: ull-array temps with .64 loads schedule cleanly (alu ~19%).
__device__ __forceinline__ void gemm_body(const float* __restrict__ row, float4 w,
                                          ull (&acc)[4][PAIRS_]) {
    const ull* h2 = (const ull*)row;
    ull hh[PAIRS_];
#pragma unroll
    for (int p = 0; p < PAIRS_; p++) hh[p] = h2[p];
    ull wi = splat2(w.x), wf = splat2(w.y), wg = splat2(w.z), wo = splat2(w.w);
#pragma unroll
    for (int p = 0; p < PAIRS_; p++) {
        acc[0][p] = ffma2(hh[p], wi, acc[0][p]);
        acc[1][p] = ffma2(hh[p], wf, acc[1][p]);
        acc[2][p] = ffma2(hh[p], wg, acc[2][p]);
        acc[3][p] = ffma2(hh[p], wo, acc[3][p]);
    }
}

// KN even. Linear pointer-increment 2-deep prefetch into padded weight region.
template <int KN>
__device__ __forceinline__ void gemm_part(const float4* __restrict__ Wcol,
                                          const float* __restrict__ Sm,
                                          ull (&acc)[4][PAIRS_]) {
    float4 wa = Wcol[0];
    float4 wb = Wcol[H_];
    const float4* Wq = Wcol + 2 * H_;
    const float*  Sr = Sm;
#pragma unroll 1
    for (int k = 0; k < KN; k += 2) {
        float4 n0 = Wq[0];
        float4 n1 = Wq[H_];
        gemm_body(Sr, wa, acc);
        gemm_body(Sr + HSTRIDE_, wb, acc);
        wa = n0;
        wb = n1;
        Wq += 2 * H_;
        Sr += 2 * HSTRIDE_;
    }
}

// Dynamic smem layout (floats):
//   S     [288][18]       : 5184 floats  (rows 0..31 = x_t, rows 32..287 = h)
//   Ex    [256][28] ull   : 14336 floats (split-k partial exchange / readout scratch)
//   WfcS  [6][256]        : 1536
//   bfcS  [8], oS [84+pad]
#define SM_S_    0
#define SM_EX_   (SM_S_ + KTOT_ * HSTRIDE_)
#define SM_WFC_  (SM_EX_ + 256 * 28 * 2)
#define SM_BFC_  (SM_WFC_ + O_ * H_)
#define SM_OS_   (SM_BFC_ + 8)
#define SM_TOTF_ (SM_OS_ + MB_ * O_ + 4)
#define SMEM_BYTES_ (SM_TOTF_ * 4)

__global__ void __launch_bounds__(NTH_, 1)
lstm_kernel(const float* __restrict__ x, const float* __restrict__ Wfc,
            const float* __restrict__ bfc, float* __restrict__ out) {
    extern __shared__ __align__(16) float smem[];
    float* S    = smem + SM_S_;
    ull*   Ex   = (ull*)(smem + SM_EX_);     // [jh][28]  (g*7 + p)
    float* WfcS = smem + SM_WFC_;
    float* bfcS = smem + SM_BFC_;
    float* oS   = smem + SM_OS_;

    const int tid = threadIdx.x;
    const int jh  = tid & 255;
    const int wg  = tid >> 8;        // k-half: 0 -> k[0,144), 1 -> k[144,288)
    const int b0  = blockIdx.x * MB_;

    for (int i = tid; i < KTOT_ * HSTRIDE_; i += NTH_) S[i] = 0.0f;
    for (int i = tid; i < O_ * H_; i += NTH_) WfcS[i] = Wfc[i];
    if (tid < O_) bfcS[tid] = bfc[tid];

    // c state: wg0 owns pairs 0..3 (rows 0..7); wg1 pairs 4..6 (rows 8..13)
    float c[8];
#pragma unroll
    for (int r = 0; r < 8; r++) c[r] = 0.0f;

    const int pbase = wg ? 4 : 0;
    const int np    = wg ? 3 : 4;

    const float4 bias = g_bias[jh];
    const float4* __restrict__ Wcol  = g_W + (size_t)(wg * KHALF_) * H_ + jh;
    const float*  __restrict__ Sbase = S + wg * KHALF_ * HSTRIDE_;

    float* Hrow  = S + (F_ + jh) * HSTRIDE_;
    ull*   ExRow = Ex + (size_t)jh * 28;

    // ---- x stager: thread slots (f, pair), 224 slots ----
    const bool stager = tid < F_ * PAIRS_;
    int xf = 0, xp = 0;
    const float* xr0 = x;
    const float* xr1 = x;
    float xa = 0.0f, xb = 0.0f;
    if (stager) {
        xf = tid / PAIRS_;
        xp = tid - xf * PAIRS_;
        int r0 = b0 + 2 * xp;     if (r0 > B_ - 1) r0 = B_ - 1;
        int r1 = b0 + 2 * xp + 1; if (r1 > B_ - 1) r1 = B_ - 1;
        xr0 = x + (size_t)r0 * S_ * F_ + xf;
        xr1 = x + (size_t)r1 * S_ * F_ + xf;
        xa = xr0[0];
        xb = xr1[0];
    }

    __syncthreads();

    for (int t = 0; t < STEPS_; t++) {
        const bool la = (t >= WARM_);

        // ---- stage x_t into S rows 0..31 (la steps override f<6 with prev output) ----
        if (stager) {
            float v0 = xa, v1 = xb;
            if (la && xf < O_) {
                v0 = oS[(2 * xp) * O_ + xf];
                v1 = oS[(2 * xp + 1) * O_ + xf];
            }
            *(ull*)(S + xf * HSTRIDE_ + 2 * xp) = pk(v0, v1);
            int tn = t + 1;
            if (tn < STEPS_) {
                int tsn = (tn < WARM_) ? tn : (tn - WARM_);
                xa = xr0[(size_t)tsn * F_];
                xb = xr1[(size_t)tsn * F_];
            }
        }
        __syncthreads();   // x rows ready; h rows stable

        // ---- split-k 4-gate GEMM over this WG's 144 k-slices ----
        ull acc[4][PAIRS_];
        if (wg == 0) {
            ull bi = splat2(bias.x), bf = splat2(bias.y),
                bg = splat2(bias.z), bo = splat2(bias.w);
#pragma unroll
            for (int p = 0; p < PAIRS_; p++) {
                acc[0][p] = bi; acc[1][p] = bf; acc[2][p] = bg; acc[3][p] = bo;
            }
        } else {
            ull z = splat2(0.0f);
#pragma unroll
            for (int p = 0; p < PAIRS_; p++) {
                acc[0][p] = z; acc[1][p] = z; acc[2][p] = z; acc[3][p] = z;
            }
        }
        gemm_part<KHALF_>(Wcol, Sbase, acc);

        // ---- exchange complement k-half partials ----
        if (wg == 0) {            // give pairs 4..6 to wg1
#pragma unroll
            for (int g = 0; g < 4; g++)
#pragma unroll
                for (int p = 4; p < 7; p++) ExRow[g * 7 + p] = acc[g][p];
        } else {                  // give pairs 0..3 to wg0
#pragma unroll
            for (int g = 0; g < 4; g++)
#pragma unroll
                for (int p = 0; p < 4; p++) ExRow[g * 7 + p] = acc[g][p];
        }
        __syncthreads();   // partials visible; all S reads complete

        // ---- reduce own pairs + elementwise cell + write new h ----
#pragma unroll
        for (int q = 0; q < 4; q++) {
            if (q >= np) break;
            int p = pbase + q;
            float2 gi = unpk(add2(acc[0][p], ExRow[0 * 7 + p]));
            float2 gf = unpk(add2(acc[1][p], ExRow[1 * 7 + p]));
            float2 gg = unpk(add2(acc[2][p], ExRow[2 * 7 + p]));
            float2 go = unpk(add2(acc[3][p], ExRow[3 * 7 + p]));
            float c0 = sigf(gf.x) * c[2 * q]     + sigf(gi.x) * tanhf(gg.x);
            float c1 = sigf(gf.y) * c[2 * q + 1] + sigf(gi.y) * tanhf(gg.y);
            c[2 * q] = c0; c[2 * q + 1] = c1;
            *(ull*)(Hrow + 2 * p) = pk(sigf(go.x) * tanhf(c0),
                                       sigf(go.y) * tanhf(c1));
        }
        __syncthreads();   // new h complete

        // ---- STE readout: out = (h>0) @ W_fc^T + b_fc  (t = 95..127) ----
        if (t >= WARM_ - 1) {
            float* red = (float*)Ex;   // scratch [84][4] (Ex dead until next exchange)
            const float* Hs = S + F_ * HSTRIDE_;
            if (tid < MB_ * O_ * 4) {
                int slot  = tid >> 2;
                int chunk = tid & 3;
                int r  = slot / O_;
                int oi = slot - r * O_;
                const float* wrow = WfcS + oi * H_;
                float s0 = 0.0f, s1 = 0.0f;
                int jb = chunk * 64;
#pragma unroll 8
                for (int j = 0; j < 64; j += 2) {
                    s0 += (Hs[(jb + j) * HSTRIDE_ + r] > 0.0f)     ? wrow[jb + j]     : 0.0f;
                    s1 += (Hs[(jb + j + 1) * HSTRIDE_ + r] > 0.0f) ? wrow[jb + j + 1] : 0.0f;
                }
                red[slot * 4 + chunk] = s0 + s1;
            }
            __syncthreads();
            if (tid < MB_ * O_) {
                int r  = tid / O_;
                int oi = tid - r * O_;
                float a = bfcS[oi] + red[tid * 4 + 0] + red[tid * 4 + 1]
                                   + red[tid * 4 + 2] + red[tid * 4 + 3];
                oS[tid] = a;
                if (b0 + r < B_)
                    out[((size_t)(b0 + r) * (LA_ + 1) + (t - (WARM_ - 1))) * O_ + oi] = a;
            }
            __syncthreads();   // oS ready; red scratch dead before next exchange
        }
    }
}

extern "C" void kernel_launch(void* const* d_in, const int* in_sizes, int n_in,
                              void* d_out, int out_size) {
    const float* x    = (const float*)d_in[0];
    const float* W_ih = (const float*)d_in[1];
    const float* W_hh = (const float*)d_in[2];
    const float* b_ih = (const float*)d_in[3];
    const float* b_hh = (const float*)d_in[4];
    const float* W_fc = (const float*)d_in[5];
    const float* b_fc = (const float*)d_in[6];
    float* out = (float*)d_out;

    cudaFuncSetAttribute(lstm_kernel, cudaFuncAttributeMaxDynamicSharedMemorySize,
                         SMEM_BYTES_);

    pack_kernel<<<(KPAD_ * H_ + 255) / 256, 256>>>(W_ih, W_hh, b_ih, b_hh);
    lstm_kernel<<<NBLK_, NTH_, SMEM_BYTES_>>>(x, W_fc, b_fc, out);
}